// round 2
// baseline (speedup 1.0000x reference)
#include <cuda_runtime.h>
#include <cuda_bf16.h>

#define T_LEN   16384
#define T_MASK  (T_LEN - 1)
#define EPS_F   1e-7f
#define BLK     256
#define NBLOCKS 1184          // 148 SMs * 8 CTAs, one full wave @ 256 thr

__device__ float g_pnum[NBLOCKS];
__device__ float g_pden[NBLOCKS];
__device__ unsigned int g_ticket = 0;

__device__ __forceinline__ float warp_sum(float v) {
#pragma unroll
    for (int o = 16; o; o >>= 1) v += __shfl_xor_sync(0xffffffffu, v, o);
    return v;
}

// log(sigmoid(x) + eps), fast-math: EX2 + RCP + LG2
__device__ __forceinline__ float log_sig_eps(float x) {
    float e = __expf(-x);
    float s = __fdividef(1.0f, 1.0f + e);
    return __logf(s + EPS_F);
}

__global__ void __launch_bounds__(BLK)
reinforce_fused(const float4* __restrict__ lp,
                const float4* __restrict__ lg,
                const float4* __restrict__ wt,
                float* __restrict__ out,
                int nvec)
{
    float num = 0.0f, den = 0.0f;
    const int stride = gridDim.x * blockDim.x;
    for (int v = blockIdx.x * blockDim.x + threadIdx.x; v < nvec; v += stride) {
        float4 a = lp[v];
        float4 b = lg[v];
        float4 c = wt[v];
        // t of element 0 in this quad; T_LEN % 4 == 0 so no wrap inside the quad
        float tb = (float)(((v << 2) & T_MASK) + 1);

        float r0 = log_sig_eps(b.x);
        float r1 = log_sig_eps(b.y);
        float r2 = log_sig_eps(b.z);
        float r3 = log_sig_eps(b.w);

        num = fmaf(c.x * c.x * r0 * a.x, tb,        num);
        num = fmaf(c.y * c.y * r1 * a.y, tb + 1.0f, num);
        num = fmaf(c.z * c.z * r2 * a.z, tb + 2.0f, num);
        num = fmaf(c.w * c.w * r3 * a.w, tb + 3.0f, num);
        den += (c.x + c.y) + (c.z + c.w);
    }

    // block reduction
    num = warp_sum(num);
    den = warp_sum(den);

    __shared__ float sn[BLK / 32], sd[BLK / 32];
    __shared__ unsigned int s_ticket;
    int wid = threadIdx.x >> 5, lid = threadIdx.x & 31;
    if (lid == 0) { sn[wid] = num; sd[wid] = den; }
    __syncthreads();
    if (threadIdx.x < BLK / 32) {
        num = sn[threadIdx.x];
        den = sd[threadIdx.x];
#pragma unroll
        for (int o = (BLK / 32) >> 1; o; o >>= 1) {
            num += __shfl_xor_sync(0xffu, num, o);
            den += __shfl_xor_sync(0xffu, den, o);
        }
        if (threadIdx.x == 0) {
            g_pnum[blockIdx.x] = num;
            g_pden[blockIdx.x] = den;
            __threadfence();                       // partials visible before ticket
            s_ticket = atomicAdd(&g_ticket, 1u);
        }
    }
    __syncthreads();

    // last block to finish reduces all partials (fixed order -> deterministic)
    if (s_ticket == (unsigned)(gridDim.x - 1)) {
        float fn = 0.0f, fd = 0.0f;
        for (int i = threadIdx.x; i < NBLOCKS; i += BLK) {
            fn += g_pnum[i];
            fd += g_pden[i];
        }
        fn = warp_sum(fn);
        fd = warp_sum(fd);
        __syncthreads();                           // reuse sn/sd safely
        if (lid == 0) { sn[wid] = fn; sd[wid] = fd; }
        __syncthreads();
        if (threadIdx.x < BLK / 32) {
            fn = sn[threadIdx.x];
            fd = sd[threadIdx.x];
#pragma unroll
            for (int o = (BLK / 32) >> 1; o; o >>= 1) {
                fn += __shfl_xor_sync(0xffu, fn, o);
                fd += __shfl_xor_sync(0xffu, fd, o);
            }
            if (threadIdx.x == 0) {
                out[0] = fn / fd;
                g_ticket = 0;                      // reset for next graph replay
            }
        }
    }
}

extern "C" void kernel_launch(void* const* d_in, const int* in_sizes, int n_in,
                              void* d_out, int out_size)
{
    const float4* lp = (const float4*)d_in[0];  // log_probs [B,T]
    const float4* lg = (const float4*)d_in[1];  // logits    [B,T,1]
    const float4* wt = (const float4*)d_in[2];  // weight    [B,T]
    float* out = (float*)d_out;

    int n = in_sizes[0];        // B*T = 8388608
    int nvec = n >> 2;

    reinforce_fused<<<NBLOCKS, BLK>>>(lp, lg, wt, out, nvec);
}